// round 3
// baseline (speedup 1.0000x reference)
#include <cuda_runtime.h>
#include <cuda_fp16.h>
#include <math.h>
#include <stdint.h>

#define B_ 2
#define S_ 2048
#define C_ 1024
#define H_ 16
#define D_ 64
#define BH_ (B_*H_)
#define L2E 1.4426950408889634f

// ---------------- scratch ----------------
__device__ __half g_xh[(size_t)B_*S_*C_];
__device__ __half g_Wqh[C_*C_];
__device__ __half g_Wkh[C_*C_];
__device__ __half g_Wvh[C_*C_];
__device__ __half g_Woh[C_*C_];
__device__ __half g_rrh[S_*D_];
__device__ __half g_Qh[(size_t)BH_*S_*D_];
__device__ __half g_Kh[(size_t)BH_*S_*D_];
__device__ __half g_Vh[(size_t)BH_*S_*D_];
__device__ float  g_T3[BH_*S_];
__device__ float  g_D[(size_t)BH_*S_*S_];
__device__ __half g_CTXh[(size_t)B_*S_*C_];

// ---------------- asm helpers ----------------
__device__ __forceinline__ uint32_t cvtsm(const void* p) {
    return (uint32_t)__cvta_generic_to_shared(p);
}
#define CP16(dst, src) asm volatile("cp.async.cg.shared.global [%0],[%1],16;\n" :: "r"(dst), "l"(src))
#define CPCOMMIT()     asm volatile("cp.async.commit_group;\n")
#define CPWAIT(n)      asm volatile("cp.async.wait_group %0;\n" :: "n"(n))

__device__ __forceinline__ void ldsm4(uint32_t& r0, uint32_t& r1, uint32_t& r2, uint32_t& r3, uint32_t a) {
    asm volatile("ldmatrix.sync.aligned.m8n8.x4.shared.b16 {%0,%1,%2,%3},[%4];\n"
                 : "=r"(r0), "=r"(r1), "=r"(r2), "=r"(r3) : "r"(a));
}
__device__ __forceinline__ void ldsm4t(uint32_t& r0, uint32_t& r1, uint32_t& r2, uint32_t& r3, uint32_t a) {
    asm volatile("ldmatrix.sync.aligned.m8n8.x4.trans.shared.b16 {%0,%1,%2,%3},[%4];\n"
                 : "=r"(r0), "=r"(r1), "=r"(r2), "=r"(r3) : "r"(a));
}
__device__ __forceinline__ void mma16(float* c, uint32_t a0, uint32_t a1, uint32_t a2, uint32_t a3,
                                      uint32_t b0, uint32_t b1) {
    asm volatile("mma.sync.aligned.m16n8k16.row.col.f32.f16.f16.f32 "
                 "{%0,%1,%2,%3},{%4,%5,%6,%7},{%8,%9},{%0,%1,%2,%3};\n"
                 : "+f"(c[0]), "+f"(c[1]), "+f"(c[2]), "+f"(c[3])
                 : "r"(a0), "r"(a1), "r"(a2), "r"(a3), "r"(b0), "r"(b1));
}
__device__ __forceinline__ uint32_t packh2(float a, float b) {
    __half2 h = __floats2half2_rn(a, b);
    return *(uint32_t*)&h;
}

// ---------------- fp32 -> fp16 convert ----------------
__global__ void f2h_kernel(const float* __restrict__ in, __half* __restrict__ out, int n) {
    int i = (blockIdx.x * blockDim.x + threadIdx.x) * 4;
    if (i < n) {
        float4 v = *(const float4*)(in + i);
        *(__half2*)(out + i)     = __floats2half2_rn(v.x, v.y);
        *(__half2*)(out + i + 2) = __floats2half2_rn(v.z, v.w);
    }
}

// ---------------- sinusoid rel-pos table (fp16) ----------------
__global__ void rr_kernel(__half* __restrict__ rr) {
    int p = blockIdx.x;
    int i = threadIdx.x;
    double invf = exp(-((double)(i & 31)) * (log(10000.0) / 32.0));
    double ang = (double)p * invf;
    float v = (i < 32) ? (float)sin(ang) : (float)cos(ang);
    rr[p * D_ + i] = __float2half(v);
}

// ---------------- fp16 GEMM NN: C = A[M,K] @ B[K,N]; mode1: half headed out; mode0: f32+bias ----------------
__global__ __launch_bounds__(256) void gemm_f16(
    const __half* __restrict__ A, const __half* __restrict__ Bm,
    const float* __restrict__ bias, void* __restrict__ Co,
    int M, int N, int K, int mode)
{
    extern __shared__ __half sm[];
    __half* As = sm;                 // [2][128][72]
    __half* Bs = sm + 2 * 128 * 72;  // [2][32][136]
    const int tid = threadIdx.x, lane = tid & 31, warp = tid >> 5;
    const int wm = warp >> 2, wn = warp & 3, grp = lane >> 2, tig = lane & 3;
    const int m0 = blockIdx.y * 128, n0 = blockIdx.x * 128;

    float acc[4][4][4];
    #pragma unroll
    for (int i = 0; i < 4; i++)
        #pragma unroll
        for (int j = 0; j < 4; j++)
            #pragma unroll
            for (int e = 0; e < 4; e++) acc[i][j][e] = 0.f;

    // copy helpers (512 16B chunks each per buffer)
    #define CPA(buf, kt) { \
        _Pragma("unroll") \
        for (int i_ = 0; i_ < 2; i_++) { int cid = tid + i_ * 256; int r = cid >> 2, c = cid & 3; \
            CP16(cvtsm(&As[(buf) * 128 * 72 + r * 72 + c * 8]), A + (size_t)(m0 + r) * K + (kt) + c * 8); } }
    #define CPB(buf, kt) { \
        _Pragma("unroll") \
        for (int i_ = 0; i_ < 2; i_++) { int cid = tid + i_ * 256; int r = cid >> 4, c = cid & 15; \
            CP16(cvtsm(&Bs[(buf) * 32 * 136 + r * 136 + c * 8]), Bm + (size_t)((kt) + r) * N + n0 + c * 8); } }

    CPA(0, 0); CPB(0, 0); CPCOMMIT();

    const int nk = K / 32;
    for (int it = 0; it < nk; it++) {
        int buf = it & 1;
        if (it + 1 < nk) { CPA(buf ^ 1, (it + 1) * 32); CPB(buf ^ 1, (it + 1) * 32); CPCOMMIT(); CPWAIT(1); }
        else CPWAIT(0);
        __syncthreads();

        #pragma unroll
        for (int kc = 0; kc < 32; kc += 16) {
            uint32_t a[4][4];
            #pragma unroll
            for (int mi = 0; mi < 4; mi++) {
                uint32_t ad = cvtsm(&As[buf * 128 * 72 + (wm * 64 + mi * 16 + (lane & 15)) * 72 + kc + 8 * (lane >> 4)]);
                ldsm4(a[mi][0], a[mi][1], a[mi][2], a[mi][3], ad);
            }
            uint32_t b[4][2];
            #pragma unroll
            for (int np = 0; np < 2; np++) {
                uint32_t ad = cvtsm(&Bs[buf * 32 * 136 + (kc + (lane & 7) + 8 * ((lane >> 3) & 1)) * 136
                                        + wn * 32 + np * 16 + 8 * (lane >> 4)]);
                uint32_t r0, r1, r2, r3;
                ldsm4t(r0, r1, r2, r3, ad);
                b[np * 2][0] = r0; b[np * 2][1] = r1;
                b[np * 2 + 1][0] = r2; b[np * 2 + 1][1] = r3;
            }
            #pragma unroll
            for (int mi = 0; mi < 4; mi++)
                #pragma unroll
                for (int ni = 0; ni < 4; ni++)
                    mma16(acc[mi][ni], a[mi][0], a[mi][1], a[mi][2], a[mi][3], b[ni][0], b[ni][1]);
        }
        __syncthreads();
    }

    #pragma unroll
    for (int mi = 0; mi < 4; mi++)
        #pragma unroll
        for (int ni = 0; ni < 4; ni++) {
            int m = m0 + wm * 64 + mi * 16 + grp;
            int n = n0 + wn * 32 + ni * 8 + tig * 2;
            if (mode == 1) {
                __half* O = (__half*)Co;
                int b = m >> 11, h = n >> 6, d = n & 63;
                int s0 = m & (S_ - 1);
                *(__half2*)&O[(((size_t)(b * H_ + h)) * S_ + s0) * D_ + d] =
                    __floats2half2_rn(acc[mi][ni][0], acc[mi][ni][1]);
                *(__half2*)&O[(((size_t)(b * H_ + h)) * S_ + s0 + 8) * D_ + d] =
                    __floats2half2_rn(acc[mi][ni][2], acc[mi][ni][3]);
            } else {
                float* O = (float*)Co;
                float b0v = bias[n], b1v = bias[n + 1];
                *(float2*)&O[(size_t)m * N + n] = make_float2(acc[mi][ni][0] + b0v, acc[mi][ni][1] + b1v);
                *(float2*)&O[(size_t)(m + 8) * N + n] = make_float2(acc[mi][ni][2] + b0v, acc[mi][ni][3] + b1v);
            }
        }
}

// ---------------- T3[bh][k] = u[h] . K[bh][k] ----------------
__global__ void t3_kernel(const __half* __restrict__ Km, const float* __restrict__ u,
                          float* __restrict__ T3)
{
    int warp = (blockIdx.x * blockDim.x + threadIdx.x) >> 5;
    int lane = threadIdx.x & 31;
    if (warp >= BH_ * S_) return;
    int bh = warp >> 11;
    int h = bh & (H_ - 1);
    const __half* kr = Km + (size_t)warp * D_;
    float s = __half2float(kr[lane]) * u[h * D_ + lane]
            + __half2float(kr[lane + 32]) * u[h * D_ + lane + 32];
    #pragma unroll
    for (int o = 16; o; o >>= 1) s += __shfl_xor_sync(0xffffffffu, s, o);
    if (lane == 0) T3[warp] = s;
}

// ---------------- D[bh][q][p] = (Q[bh][q]+v[h]) . rr[p] ; fp16 mma, fp32 out ----------------
__global__ __launch_bounds__(256) void relD_f16(
    const __half* __restrict__ Qh, const __half* __restrict__ rrh,
    const float* __restrict__ vb, float* __restrict__ D)
{
    __shared__ __half As[128 * 72];
    __shared__ __half Bs[128 * 72];
    const int bh = blockIdx.z, h = bh & (H_ - 1);
    const int q0 = blockIdx.y * 128, p0 = blockIdx.x * 128;
    const __half* Aq = Qh + (size_t)bh * S_ * D_;
    const int tid = threadIdx.x, lane = tid & 31, warp = tid >> 5;
    const int wm = warp >> 2, wn = warp & 3, grp = lane >> 2, tig = lane & 3;

    // A = Q + v  (fp32 math, round to fp16)
    {
        int r = tid >> 1, off = (tid & 1) * 32;
        const __half* src = Aq + (size_t)(q0 + r) * D_ + off;
        #pragma unroll
        for (int i = 0; i < 32; i += 2) {
            float2 qv = __half22float2(*(const __half2*)(src + i));
            float2 vv = *(const float2*)(vb + h * D_ + off + i);
            *(__half2*)&As[r * 72 + off + i] = __floats2half2_rn(qv.x + vv.x, qv.y + vv.y);
        }
    }
    // B = rr tile (direct 16B copies)
    #pragma unroll
    for (int i = 0; i < 4; i++) {
        int cid = tid + i * 256;
        int r = cid >> 3, c = cid & 7;
        *(uint4*)&Bs[r * 72 + c * 8] = *(const uint4*)(rrh + (size_t)(p0 + r) * D_ + c * 8);
    }
    __syncthreads();

    float acc[4][4][4];
    #pragma unroll
    for (int i = 0; i < 4; i++)
        #pragma unroll
        for (int j = 0; j < 4; j++)
            #pragma unroll
            for (int e = 0; e < 4; e++) acc[i][j][e] = 0.f;

    #pragma unroll
    for (int kc = 0; kc < 64; kc += 16) {
        uint32_t a[4][4];
        #pragma unroll
        for (int mi = 0; mi < 4; mi++) {
            uint32_t ad = cvtsm(&As[(wm * 64 + mi * 16 + (lane & 15)) * 72 + kc + 8 * (lane >> 4)]);
            ldsm4(a[mi][0], a[mi][1], a[mi][2], a[mi][3], ad);
        }
        uint32_t b[4][2];
        #pragma unroll
        for (int np = 0; np < 2; np++) {
            uint32_t ad = cvtsm(&Bs[(wn * 32 + np * 16 + (lane & 7) + 8 * (lane >> 4)) * 72
                                    + kc + 8 * ((lane >> 3) & 1)]);
            uint32_t r0, r1, r2, r3;
            ldsm4(r0, r1, r2, r3, ad);
            b[np * 2][0] = r0; b[np * 2][1] = r1;
            b[np * 2 + 1][0] = r2; b[np * 2 + 1][1] = r3;
        }
        #pragma unroll
        for (int mi = 0; mi < 4; mi++)
            #pragma unroll
            for (int ni = 0; ni < 4; ni++)
                mma16(acc[mi][ni], a[mi][0], a[mi][1], a[mi][2], a[mi][3], b[ni][0], b[ni][1]);
    }

    float* Dp = D + (size_t)bh * S_ * S_;
    #pragma unroll
    for (int mi = 0; mi < 4; mi++)
        #pragma unroll
        for (int ni = 0; ni < 4; ni++) {
            int q = q0 + wm * 64 + mi * 16 + grp;
            int p = p0 + wn * 32 + ni * 8 + tig * 2;
            *(float2*)&Dp[(size_t)q * S_ + p] = make_float2(acc[mi][ni][0], acc[mi][ni][1]);
            *(float2*)&Dp[(size_t)(q + 8) * S_ + p] = make_float2(acc[mi][ni][2], acc[mi][ni][3]);
        }
}

// ---------------- fused flash attention: scores + shift + softmax + PV ----------------
__global__ __launch_bounds__(256) void flash_kernel(
    const __half* __restrict__ Qh, const __half* __restrict__ Kh, const __half* __restrict__ Vh,
    const float* __restrict__ T3, const float* __restrict__ Dg, __half* __restrict__ CTXh)
{
    extern __shared__ __half sm[];
    __half* Qs = sm;                          // [128][72]
    __half* Ks = sm + 128 * 72;               // [2][128][72]
    __half* Vs = Ks + 2 * 128 * 72;           // [2][128][72]
    float*  T3s = (float*)(Vs + 2 * 128 * 72);// [2][128]

    const int bh = blockIdx.y, b = bh >> 4, h = bh & 15;
    const int q0 = blockIdx.x * 128;
    const __half* Qg = Qh + (size_t)bh * S_ * D_;
    const __half* Kg = Kh + (size_t)bh * S_ * D_;
    const __half* Vg = Vh + (size_t)bh * S_ * D_;
    const float* Dp = Dg + (size_t)bh * S_ * S_;
    const float* t3g = T3 + bh * S_;
    const int tid = threadIdx.x, lane = tid & 31, warp = tid >> 5;
    const int grp = lane >> 2, tig = lane & 3;
    const int wrow = warp * 16;

    // Q tile copy
    #pragma unroll
    for (int i = 0; i < 4; i++) {
        int cid = tid + i * 256, r = cid >> 3, c = cid & 7;
        CP16(cvtsm(&Qs[r * 72 + c * 8]), Qg + (size_t)(q0 + r) * D_ + c * 8);
    }
    #define CPKV(buf, k0t) { \
        _Pragma("unroll") \
        for (int i_ = 0; i_ < 4; i_++) { int cid = tid + i_ * 256, r = cid >> 3, c = cid & 7; \
            CP16(cvtsm(&Ks[(buf) * 9216 + r * 72 + c * 8]), Kg + (size_t)((k0t) + r) * D_ + c * 8); } \
        _Pragma("unroll") \
        for (int i_ = 0; i_ < 4; i_++) { int cid = tid + i_ * 256, r = cid >> 3, c = cid & 7; \
            CP16(cvtsm(&Vs[(buf) * 9216 + r * 72 + c * 8]), Vg + (size_t)((k0t) + r) * D_ + c * 8); } \
        if (tid < 32) CP16(cvtsm(&T3s[(buf) * 128 + tid * 4]), t3g + (k0t) + tid * 4); }

    CPKV(0, 0); CPCOMMIT();
    CPWAIT(0);
    __syncthreads();

    // resident Q fragments (16 rows x 64 k)
    uint32_t aQ[4][4];
    #pragma unroll
    for (int kc = 0; kc < 4; kc++) {
        uint32_t ad = cvtsm(&Qs[(wrow + (lane & 15)) * 72 + kc * 16 + 8 * (lane >> 4)]);
        ldsm4(aQ[kc][0], aQ[kc][1], aQ[kc][2], aQ[kc][3], ad);
    }

    float Oa[8][4];
    #pragma unroll
    for (int i = 0; i < 8; i++)
        #pragma unroll
        for (int e = 0; e < 4; e++) Oa[i][e] = 0.f;
    float m0r = -1e30f, m1r = -1e30f, l0r = 0.f, l1r = 0.f;
    const int qr0 = q0 + wrow + grp, qr1 = qr0 + 8;

    for (int kt = 0; kt < 16; kt++) {
        const int buf = kt & 1;
        const int k0 = kt * 128;
        if (kt < 15) { CPKV(buf ^ 1, (kt + 1) * 128); CPCOMMIT(); CPWAIT(1); }
        else CPWAIT(0);
        __syncthreads();

        // S = Q @ K^T  (16 rows x 128 cols per warp)
        float sc[16][4];
        #pragma unroll
        for (int i = 0; i < 16; i++)
            #pragma unroll
            for (int e = 0; e < 4; e++) sc[i][e] = 0.f;
        #pragma unroll
        for (int ntp = 0; ntp < 8; ntp++) {
            #pragma unroll
            for (int kc = 0; kc < 4; kc++) {
                uint32_t ad = cvtsm(&Ks[buf * 9216 + (ntp * 16 + (lane & 7) + 8 * (lane >> 4)) * 72
                                        + kc * 16 + 8 * ((lane >> 3) & 1)]);
                uint32_t r0, r1, r2, r3;
                ldsm4(r0, r1, r2, r3, ad);
                mma16(sc[ntp * 2], aQ[kc][0], aQ[kc][1], aQ[kc][2], aQ[kc][3], r0, r1);
                mma16(sc[ntp * 2 + 1], aQ[kc][0], aQ[kc][1], aQ[kc][2], aQ[kc][3], r2, r3);
            }
        }

        // epilogue: + t3 + rel_shift(D), scale, online softmax
        float mx0 = -1e30f, mx1 = -1e30f;
        #pragma unroll
        for (int nt = 0; nt < 16; nt++) {
            int kc0 = k0 + nt * 8 + tig * 2;
            float2 t3v = *(float2*)&T3s[buf * 128 + nt * 8 + tig * 2];
            #pragma unroll
            for (int e = 0; e < 4; e++) {
                int q = (e < 2) ? qr0 : qr1;
                int k = kc0 + (e & 1);
                int dq = q - k;
                float sh;
                if (dq >= 0)       sh = Dp[(size_t)q * S_ + dq];
                else if (dq == -1) sh = 0.f;
                else               sh = Dp[(size_t)(q + 1) * S_ + (S_ + 1 + dq)];
                float t3x = (e & 1) ? t3v.y : t3v.x;
                sc[nt][e] = (sc[nt][e] + t3x + sh) * 0.125f;
            }
            mx0 = fmaxf(mx0, fmaxf(sc[nt][0], sc[nt][1]));
            mx1 = fmaxf(mx1, fmaxf(sc[nt][2], sc[nt][3]));
        }
        mx0 = fmaxf(mx0, __shfl_xor_sync(0xffffffffu, mx0, 1));
        mx0 = fmaxf(mx0, __shfl_xor_sync(0xffffffffu, mx0, 2));
        mx1 = fmaxf(mx1, __shfl_xor_sync(0xffffffffu, mx1, 1));
        mx1 = fmaxf(mx1, __shfl_xor_sync(0xffffffffu, mx1, 2));
        float mn0 = fmaxf(m0r, mx0), mn1 = fmaxf(m1r, mx1);
        float al0 = exp2f((m0r - mn0) * L2E), al1 = exp2f((m1r - mn1) * L2E);
        m0r = mn0; m1r = mn1;

        float sum0 = 0.f, sum1 = 0.f;
        uint32_t hP[16][2];
        #pragma unroll
        for (int nt = 0; nt < 16; nt++) {
            float p0 = exp2f((sc[nt][0] - mn0) * L2E);
            float p1 = exp2f((sc[nt][1] - mn0) * L2E);
            float p2 = exp2f((sc[nt][2] - mn1) * L2E);
            float p3 = exp2f((sc[nt][3] - mn1) * L2E);
            sum0 += p0 + p1; sum1 += p2 + p3;
            hP[nt][0] = packh2(p0, p1);
            hP[nt][1] = packh2(p2, p3);
        }
        sum0 += __shfl_xor_sync(0xffffffffu, sum0, 1);
        sum0 += __shfl_xor_sync(0xffffffffu, sum0, 2);
        sum1 += __shfl_xor_sync(0xffffffffu, sum1, 1);
        sum1 += __shfl_xor_sync(0xffffffffu, sum1, 2);
        l0r = l0r * al0 + sum0;
        l1r = l1r * al1 + sum1;
        #pragma unroll
        for (int nd = 0; nd < 8; nd++) {
            Oa[nd][0] *= al0; Oa[nd][1] *= al0;
            Oa[nd][2] *= al1; Oa[nd][3] *= al1;
        }

        // O += P @ V
        #pragma unroll
        for (int j = 0; j < 8; j++) {
            uint32_t pa0 = hP[2 * j][0], pa1 = hP[2 * j][1];
            uint32_t pa2 = hP[2 * j + 1][0], pa3 = hP[2 * j + 1][1];
            #pragma unroll
            for (int dp = 0; dp < 4; dp++) {
                uint32_t ad = cvtsm(&Vs[buf * 9216 + (j * 16 + (lane & 15)) * 72
                                        + dp * 16 + 8 * (lane >> 4)]);
                uint32_t r0, r1, r2, r3;
                ldsm4t(r0, r1, r2, r3, ad);
                mma16(Oa[dp * 2], pa0, pa1, pa2, pa3, r0, r1);
                mma16(Oa[dp * 2 + 1], pa0, pa1, pa2, pa3, r2, r3);
            }
        }
        __syncthreads();
    }

    float inv0 = 1.f / l0r, inv1 = 1.f / l1r;
    #pragma unroll
    for (int nd = 0; nd < 8; nd++) {
        int d = nd * 8 + tig * 2;
        *(__half2*)&CTXh[((size_t)b * S_ + qr0) * C_ + h * D_ + d] =
            __floats2half2_rn(Oa[nd][0] * inv0, Oa[nd][1] * inv0);
        *(__half2*)&CTXh[((size_t)b * S_ + qr1) * C_ + h * D_ + d] =
            __floats2half2_rn(Oa[nd][2] * inv1, Oa[nd][3] * inv1);
    }
}

// ---------------- launch ----------------
extern "C" void kernel_launch(void* const* d_in, const int* in_sizes, int n_in,
                              void* d_out, int out_size)
{
    const float* x  = (const float*)d_in[0];
    const float* Wq = (const float*)d_in[1];
    const float* Wk = (const float*)d_in[2];
    const float* Wv = (const float*)d_in[3];
    const float* u  = (const float*)d_in[4];
    const float* v  = (const float*)d_in[5];
    const float* Wo = (const float*)d_in[6];
    const float* bo = (const float*)d_in[7];
    float* out = (float*)d_out;

    __half *xh, *Wqh, *Wkh, *Wvh, *Woh, *rrh, *Qh, *Kh, *Vh, *CTXh;
    float *T3, *D;
    cudaGetSymbolAddress((void**)&xh,   g_xh);
    cudaGetSymbolAddress((void**)&Wqh,  g_Wqh);
    cudaGetSymbolAddress((void**)&Wkh,  g_Wkh);
    cudaGetSymbolAddress((void**)&Wvh,  g_Wvh);
    cudaGetSymbolAddress((void**)&Woh,  g_Woh);
    cudaGetSymbolAddress((void**)&rrh,  g_rrh);
    cudaGetSymbolAddress((void**)&Qh,   g_Qh);
    cudaGetSymbolAddress((void**)&Kh,   g_Kh);
    cudaGetSymbolAddress((void**)&Vh,   g_Vh);
    cudaGetSymbolAddress((void**)&T3,   g_T3);
    cudaGetSymbolAddress((void**)&D,    g_D);
    cudaGetSymbolAddress((void**)&CTXh, g_CTXh);

    static int smem_set = 0;
    const int SMEMP = 2 * 128 * 72 * 2 + 2 * 32 * 136 * 2;              // 54272
    const int SMEMF = 128 * 72 * 2 + 4 * 128 * 72 * 2 + 2 * 128 * 4;    // 93184
    if (!smem_set) {
        cudaFuncSetAttribute(gemm_f16, cudaFuncAttributeMaxDynamicSharedMemorySize, SMEMP);
        cudaFuncSetAttribute(flash_kernel, cudaFuncAttributeMaxDynamicSharedMemorySize, SMEMF);
        smem_set = 1;
    }

    const int NXE = B_ * S_ * C_;   // 4194304
    f2h_kernel<<<NXE / 1024, 256>>>(x, xh, NXE);
    f2h_kernel<<<1024, 256>>>(Wq, Wqh, C_ * C_);
    f2h_kernel<<<1024, 256>>>(Wk, Wkh, C_ * C_);
    f2h_kernel<<<1024, 256>>>(Wv, Wvh, C_ * C_);
    f2h_kernel<<<1024, 256>>>(Wo, Woh, C_ * C_);
    rr_kernel<<<S_, 64>>>(rrh);

    dim3 gproj(C_ / 128, (B_ * S_) / 128);
    gemm_f16<<<gproj, 256, SMEMP>>>(xh, Wqh, nullptr, Qh, B_ * S_, C_, C_, 1);
    gemm_f16<<<gproj, 256, SMEMP>>>(xh, Wkh, nullptr, Kh, B_ * S_, C_, C_, 1);
    gemm_f16<<<gproj, 256, SMEMP>>>(xh, Wvh, nullptr, Vh, B_ * S_, C_, C_, 1);

    t3_kernel<<<(BH_ * S_ * 32) / 256, 256>>>(Kh, u, T3);

    dim3 gd(S_ / 128, S_ / 128, BH_);
    relD_f16<<<gd, 256>>>(Qh, rrh, v, D);

    dim3 gfl(S_ / 128, BH_);
    flash_kernel<<<gfl, 256, SMEMF>>>(Qh, Kh, Vh, T3, D, CTXh);

    gemm_f16<<<gproj, 256, SMEMP>>>(CTXh, Woh, bo, out, B_ * S_, C_, C_, 0);
}

// round 4
// speedup vs baseline: 1.7242x; 1.7242x over previous
#include <cuda_runtime.h>
#include <cuda_fp16.h>
#include <math.h>
#include <stdint.h>

#define B_ 2
#define S_ 2048
#define C_ 1024
#define H_ 16
#define D_ 64
#define BH_ (B_*H_)
#define L2E 1.4426950408889634f

// ---------------- scratch ----------------
__device__ __half g_xh[(size_t)B_*S_*C_];
__device__ __half g_Wqh[C_*C_];
__device__ __half g_Wkh[C_*C_];
__device__ __half g_Wvh[C_*C_];
__device__ __half g_Woh[C_*C_];
__device__ __half g_rrh[S_*D_];
__device__ __half g_Qh[(size_t)BH_*S_*D_];
__device__ __half g_Kh[(size_t)BH_*S_*D_];
__device__ __half g_Vh[(size_t)BH_*S_*D_];
__device__ float  g_T3[BH_*S_];
__device__ float  g_D[(size_t)BH_*S_*S_];
__device__ __half g_CTXh[(size_t)B_*S_*C_];

// ---------------- asm helpers ----------------
__device__ __forceinline__ uint32_t cvtsm(const void* p) {
    return (uint32_t)__cvta_generic_to_shared(p);
}
#define CP16(dst, src) asm volatile("cp.async.cg.shared.global [%0],[%1],16;\n" :: "r"(dst), "l"(src))
#define CPCOMMIT()     asm volatile("cp.async.commit_group;\n")
#define CPWAIT(n)      asm volatile("cp.async.wait_group %0;\n" :: "n"(n))

__device__ __forceinline__ void ldsm4(uint32_t& r0, uint32_t& r1, uint32_t& r2, uint32_t& r3, uint32_t a) {
    asm volatile("ldmatrix.sync.aligned.m8n8.x4.shared.b16 {%0,%1,%2,%3},[%4];\n"
                 : "=r"(r0), "=r"(r1), "=r"(r2), "=r"(r3) : "r"(a));
}
__device__ __forceinline__ void ldsm4t(uint32_t& r0, uint32_t& r1, uint32_t& r2, uint32_t& r3, uint32_t a) {
    asm volatile("ldmatrix.sync.aligned.m8n8.x4.trans.shared.b16 {%0,%1,%2,%3},[%4];\n"
                 : "=r"(r0), "=r"(r1), "=r"(r2), "=r"(r3) : "r"(a));
}
__device__ __forceinline__ void mma16(float* c, uint32_t a0, uint32_t a1, uint32_t a2, uint32_t a3,
                                      uint32_t b0, uint32_t b1) {
    asm volatile("mma.sync.aligned.m16n8k16.row.col.f32.f16.f16.f32 "
                 "{%0,%1,%2,%3},{%4,%5,%6,%7},{%8,%9},{%0,%1,%2,%3};\n"
                 : "+f"(c[0]), "+f"(c[1]), "+f"(c[2]), "+f"(c[3])
                 : "r"(a0), "r"(a1), "r"(a2), "r"(a3), "r"(b0), "r"(b1));
}
__device__ __forceinline__ uint32_t packh2(float a, float b) {
    __half2 h = __floats2half2_rn(a, b);
    return *(uint32_t*)&h;
}

// ---------------- fused fp32 -> fp16 convert (x + 4 weights) ----------------
__global__ void cvt_all(const float* __restrict__ x,  const float* __restrict__ Wq,
                        const float* __restrict__ Wk, const float* __restrict__ Wv,
                        const float* __restrict__ Wo,
                        __half* __restrict__ xh,  __half* __restrict__ Wqh,
                        __half* __restrict__ Wkh, __half* __restrict__ Wvh,
                        __half* __restrict__ Woh)
{
    int i = (blockIdx.x * blockDim.x + threadIdx.x) * 4;
    const float* src; __half* dst; int off;
    const int NX = B_ * S_ * C_;            // 4194304
    const int NW = C_ * C_;                 // 1048576
    if (i < NX)               { src = x;  dst = xh;  off = i; }
    else if (i < NX + NW)     { src = Wq; dst = Wqh; off = i - NX; }
    else if (i < NX + 2 * NW) { src = Wk; dst = Wkh; off = i - NX - NW; }
    else if (i < NX + 3 * NW) { src = Wv; dst = Wvh; off = i - NX - 2 * NW; }
    else                      { src = Wo; dst = Woh; off = i - NX - 3 * NW; }
    float4 v = *(const float4*)(src + off);
    *(__half2*)(dst + off)     = __floats2half2_rn(v.x, v.y);
    *(__half2*)(dst + off + 2) = __floats2half2_rn(v.z, v.w);
}

// ---------------- sinusoid rel-pos table (fp16) ----------------
__global__ void rr_kernel(__half* __restrict__ rr) {
    int p = blockIdx.x;
    int i = threadIdx.x;
    double invf = exp(-((double)(i & 31)) * (log(10000.0) / 32.0));
    double ang = (double)p * invf;
    float v = (i < 32) ? (float)sin(ang) : (float)cos(ang);
    rr[p * D_ + i] = __float2half(v);
}

// ---------------- fp16 GEMM NN: C = A[M,K] @ B[K,N]; mode1: half headed out; mode0: f32+bias ----------------
__global__ __launch_bounds__(256) void gemm_f16(
    const __half* __restrict__ A, const __half* __restrict__ Bm,
    const float* __restrict__ bias, void* __restrict__ Co,
    int M, int N, int K, int mode)
{
    extern __shared__ __half sm[];
    __half* As = sm;                 // [2][128][72]
    __half* Bs = sm + 2 * 128 * 72;  // [2][32][136]
    const int tid = threadIdx.x, lane = tid & 31, warp = tid >> 5;
    const int wm = warp >> 2, wn = warp & 3, grp = lane >> 2, tig = lane & 3;
    const int m0 = blockIdx.y * 128, n0 = blockIdx.x * 128;

    float acc[4][4][4];
    #pragma unroll
    for (int i = 0; i < 4; i++)
        #pragma unroll
        for (int j = 0; j < 4; j++)
            #pragma unroll
            for (int e = 0; e < 4; e++) acc[i][j][e] = 0.f;

    #define CPA(buf, kt) { \
        _Pragma("unroll") \
        for (int i_ = 0; i_ < 2; i_++) { int cid = tid + i_ * 256; int r = cid >> 2, c = cid & 3; \
            CP16(cvtsm(&As[(buf) * 128 * 72 + r * 72 + c * 8]), A + (size_t)(m0 + r) * K + (kt) + c * 8); } }
    #define CPB(buf, kt) { \
        _Pragma("unroll") \
        for (int i_ = 0; i_ < 2; i_++) { int cid = tid + i_ * 256; int r = cid >> 4, c = cid & 15; \
            CP16(cvtsm(&Bs[(buf) * 32 * 136 + r * 136 + c * 8]), Bm + (size_t)((kt) + r) * N + n0 + c * 8); } }

    CPA(0, 0); CPB(0, 0); CPCOMMIT();

    const int nk = K / 32;
    for (int it = 0; it < nk; it++) {
        int buf = it & 1;
        if (it + 1 < nk) { CPA(buf ^ 1, (it + 1) * 32); CPB(buf ^ 1, (it + 1) * 32); CPCOMMIT(); CPWAIT(1); }
        else CPWAIT(0);
        __syncthreads();

        #pragma unroll
        for (int kc = 0; kc < 32; kc += 16) {
            uint32_t a[4][4];
            #pragma unroll
            for (int mi = 0; mi < 4; mi++) {
                uint32_t ad = cvtsm(&As[buf * 128 * 72 + (wm * 64 + mi * 16 + (lane & 15)) * 72 + kc + 8 * (lane >> 4)]);
                ldsm4(a[mi][0], a[mi][1], a[mi][2], a[mi][3], ad);
            }
            uint32_t b[4][2];
            #pragma unroll
            for (int np = 0; np < 2; np++) {
                uint32_t ad = cvtsm(&Bs[buf * 32 * 136 + (kc + (lane & 7) + 8 * ((lane >> 3) & 1)) * 136
                                        + wn * 32 + np * 16 + 8 * (lane >> 4)]);
                uint32_t r0, r1, r2, r3;
                ldsm4t(r0, r1, r2, r3, ad);
                b[np * 2][0] = r0; b[np * 2][1] = r1;
                b[np * 2 + 1][0] = r2; b[np * 2 + 1][1] = r3;
            }
            #pragma unroll
            for (int mi = 0; mi < 4; mi++)
                #pragma unroll
                for (int ni = 0; ni < 4; ni++)
                    mma16(acc[mi][ni], a[mi][0], a[mi][1], a[mi][2], a[mi][3], b[ni][0], b[ni][1]);
        }
        __syncthreads();
    }

    #pragma unroll
    for (int mi = 0; mi < 4; mi++)
        #pragma unroll
        for (int ni = 0; ni < 4; ni++) {
            int m = m0 + wm * 64 + mi * 16 + grp;
            int n = n0 + wn * 32 + ni * 8 + tig * 2;
            if (mode == 1) {
                __half* O = (__half*)Co;
                int b = m >> 11, h = n >> 6, d = n & 63;
                int s0 = m & (S_ - 1);
                *(__half2*)&O[(((size_t)(b * H_ + h)) * S_ + s0) * D_ + d] =
                    __floats2half2_rn(acc[mi][ni][0], acc[mi][ni][1]);
                *(__half2*)&O[(((size_t)(b * H_ + h)) * S_ + s0 + 8) * D_ + d] =
                    __floats2half2_rn(acc[mi][ni][2], acc[mi][ni][3]);
            } else {
                float* O = (float*)Co;
                float b0v = bias[n], b1v = bias[n + 1];
                *(float2*)&O[(size_t)m * N + n] = make_float2(acc[mi][ni][0] + b0v, acc[mi][ni][1] + b1v);
                *(float2*)&O[(size_t)(m + 8) * N + n] = make_float2(acc[mi][ni][2] + b0v, acc[mi][ni][3] + b1v);
            }
        }
}

// ---------------- T3[bh][k] = u[h] . K[bh][k] ----------------
__global__ void t3_kernel(const __half* __restrict__ Km, const float* __restrict__ u,
                          float* __restrict__ T3)
{
    int warp = (blockIdx.x * blockDim.x + threadIdx.x) >> 5;
    int lane = threadIdx.x & 31;
    if (warp >= BH_ * S_) return;
    int bh = warp >> 11;
    int h = bh & (H_ - 1);
    const __half* kr = Km + (size_t)warp * D_;
    float s = __half2float(kr[lane]) * u[h * D_ + lane]
            + __half2float(kr[lane + 32]) * u[h * D_ + lane + 32];
    #pragma unroll
    for (int o = 16; o; o >>= 1) s += __shfl_xor_sync(0xffffffffu, s, o);
    if (lane == 0) T3[warp] = s;
}

// ---------------- D[bh][q][p] = (Q[bh][q]+v[h]) . rr[p] ; fp16 mma, fp32 out ----------------
__global__ __launch_bounds__(256) void relD_f16(
    const __half* __restrict__ Qh, const __half* __restrict__ rrh,
    const float* __restrict__ vb, float* __restrict__ D)
{
    __shared__ __half As[128 * 72];
    __shared__ __half Bs[128 * 72];
    const int bh = blockIdx.z, h = bh & (H_ - 1);
    const int q0 = blockIdx.y * 128, p0 = blockIdx.x * 128;
    const __half* Aq = Qh + (size_t)bh * S_ * D_;
    const int tid = threadIdx.x, lane = tid & 31, warp = tid >> 5;
    const int wm = warp >> 2, wn = warp & 3, grp = lane >> 2, tig = lane & 3;

    {
        int r = tid >> 1, off = (tid & 1) * 32;
        const __half* src = Aq + (size_t)(q0 + r) * D_ + off;
        #pragma unroll
        for (int i = 0; i < 32; i += 2) {
            float2 qv = __half22float2(*(const __half2*)(src + i));
            float2 vv = *(const float2*)(vb + h * D_ + off + i);
            *(__half2*)&As[r * 72 + off + i] = __floats2half2_rn(qv.x + vv.x, qv.y + vv.y);
        }
    }
    #pragma unroll
    for (int i = 0; i < 4; i++) {
        int cid = tid + i * 256;
        int r = cid >> 3, c = cid & 7;
        *(uint4*)&Bs[r * 72 + c * 8] = *(const uint4*)(rrh + (size_t)(p0 + r) * D_ + c * 8);
    }
    __syncthreads();

    float acc[4][4][4];
    #pragma unroll
    for (int i = 0; i < 4; i++)
        #pragma unroll
        for (int j = 0; j < 4; j++)
            #pragma unroll
            for (int e = 0; e < 4; e++) acc[i][j][e] = 0.f;

    #pragma unroll
    for (int kc = 0; kc < 64; kc += 16) {
        uint32_t a[4][4];
        #pragma unroll
        for (int mi = 0; mi < 4; mi++) {
            uint32_t ad = cvtsm(&As[(wm * 64 + mi * 16 + (lane & 15)) * 72 + kc + 8 * (lane >> 4)]);
            ldsm4(a[mi][0], a[mi][1], a[mi][2], a[mi][3], ad);
        }
        uint32_t b[4][2];
        #pragma unroll
        for (int np = 0; np < 2; np++) {
            uint32_t ad = cvtsm(&Bs[(wn * 32 + np * 16 + (lane & 7) + 8 * (lane >> 4)) * 72
                                    + kc + 8 * ((lane >> 3) & 1)]);
            uint32_t r0, r1, r2, r3;
            ldsm4(r0, r1, r2, r3, ad);
            b[np * 2][0] = r0; b[np * 2][1] = r1;
            b[np * 2 + 1][0] = r2; b[np * 2 + 1][1] = r3;
        }
        #pragma unroll
        for (int mi = 0; mi < 4; mi++)
            #pragma unroll
            for (int ni = 0; ni < 4; ni++)
                mma16(acc[mi][ni], a[mi][0], a[mi][1], a[mi][2], a[mi][3], b[ni][0], b[ni][1]);
    }

    float* Dp = D + (size_t)bh * S_ * S_;
    #pragma unroll
    for (int mi = 0; mi < 4; mi++)
        #pragma unroll
        for (int ni = 0; ni < 4; ni++) {
            int q = q0 + wm * 64 + mi * 16 + grp;
            int p = p0 + wn * 32 + ni * 8 + tig * 2;
            *(float2*)&Dp[(size_t)q * S_ + p] = make_float2(acc[mi][ni][0], acc[mi][ni][1]);
            *(float2*)&Dp[(size_t)(q + 8) * S_ + p] = make_float2(acc[mi][ni][2], acc[mi][ni][3]);
        }
}

// ---------------- fused flash attention: BM=128, BN=64, 2 CTAs/SM ----------------
__global__ __launch_bounds__(256, 2) void flash_kernel(
    const __half* __restrict__ Qh, const __half* __restrict__ Kh, const __half* __restrict__ Vh,
    const float* __restrict__ T3, const float* __restrict__ Dg, __half* __restrict__ CTXh)
{
    extern __shared__ __half sm[];
    __half* Qs = sm;                           // [128][72]
    __half* Ks = sm + 128 * 72;                // [2][64][72]
    __half* Vs = Ks + 2 * 64 * 72;             // [2][64][72]
    float*  T3s = (float*)(Vs + 2 * 64 * 72);  // [2][64]

    const int bh = blockIdx.y, b = bh >> 4, h = bh & 15;
    const int q0 = blockIdx.x * 128;
    const __half* Qg = Qh + (size_t)bh * S_ * D_;
    const __half* Kg = Kh + (size_t)bh * S_ * D_;
    const __half* Vg = Vh + (size_t)bh * S_ * D_;
    const float* Dp = Dg + (size_t)bh * S_ * S_;
    const float* t3g = T3 + bh * S_;
    const int tid = threadIdx.x, lane = tid & 31, warp = tid >> 5;
    const int grp = lane >> 2, tig = lane & 3;
    const int wrow = warp * 16;

    #pragma unroll
    for (int i = 0; i < 4; i++) {
        int cid = tid + i * 256, r = cid >> 3, c = cid & 7;
        CP16(cvtsm(&Qs[r * 72 + c * 8]), Qg + (size_t)(q0 + r) * D_ + c * 8);
    }
    #define CPKV(buf, k0t) { \
        _Pragma("unroll") \
        for (int i_ = 0; i_ < 2; i_++) { int cid = tid + i_ * 256, r = cid >> 3, c = cid & 7; \
            CP16(cvtsm(&Ks[(buf) * 4608 + r * 72 + c * 8]), Kg + (size_t)((k0t) + r) * D_ + c * 8); } \
        _Pragma("unroll") \
        for (int i_ = 0; i_ < 2; i_++) { int cid = tid + i_ * 256, r = cid >> 3, c = cid & 7; \
            CP16(cvtsm(&Vs[(buf) * 4608 + r * 72 + c * 8]), Vg + (size_t)((k0t) + r) * D_ + c * 8); } \
        if (tid < 16) CP16(cvtsm(&T3s[(buf) * 64 + tid * 4]), t3g + (k0t) + tid * 4); }

    CPKV(0, 0); CPCOMMIT();
    CPWAIT(0);
    __syncthreads();

    uint32_t aQ[4][4];
    #pragma unroll
    for (int kc = 0; kc < 4; kc++) {
        uint32_t ad = cvtsm(&Qs[(wrow + (lane & 15)) * 72 + kc * 16 + 8 * (lane >> 4)]);
        ldsm4(aQ[kc][0], aQ[kc][1], aQ[kc][2], aQ[kc][3], ad);
    }

    float Oa[8][4];
    #pragma unroll
    for (int i = 0; i < 8; i++)
        #pragma unroll
        for (int e = 0; e < 4; e++) Oa[i][e] = 0.f;
    float m0r = -1e30f, m1r = -1e30f, l0r = 0.f, l1r = 0.f;
    const int qr0 = q0 + wrow + grp, qr1 = qr0 + 8;

    for (int kt = 0; kt < 32; kt++) {
        const int buf = kt & 1;
        const int k0 = kt * 64;
        if (kt < 31) { CPKV(buf ^ 1, (kt + 1) * 64); CPCOMMIT(); CPWAIT(1); }
        else CPWAIT(0);
        __syncthreads();

        // S = Q @ K^T  (16 rows x 64 cols per warp)
        float sc[8][4];
        #pragma unroll
        for (int i = 0; i < 8; i++)
            #pragma unroll
            for (int e = 0; e < 4; e++) sc[i][e] = 0.f;
        #pragma unroll
        for (int ntp = 0; ntp < 4; ntp++) {
            #pragma unroll
            for (int kc = 0; kc < 4; kc++) {
                uint32_t ad = cvtsm(&Ks[buf * 4608 + (ntp * 16 + (lane & 7) + 8 * (lane >> 4)) * 72
                                        + kc * 16 + 8 * ((lane >> 3) & 1)]);
                uint32_t r0, r1, r2, r3;
                ldsm4(r0, r1, r2, r3, ad);
                mma16(sc[ntp * 2], aQ[kc][0], aQ[kc][1], aQ[kc][2], aQ[kc][3], r0, r1);
                mma16(sc[ntp * 2 + 1], aQ[kc][0], aQ[kc][1], aQ[kc][2], aQ[kc][3], r2, r3);
            }
        }

        // epilogue: + t3 + rel_shift(D), scale, online softmax
        float mx0 = -1e30f, mx1 = -1e30f;
        #pragma unroll
        for (int nt = 0; nt < 8; nt++) {
            int kc0 = k0 + nt * 8 + tig * 2;
            float2 t3v = *(float2*)&T3s[buf * 64 + nt * 8 + tig * 2];
            #pragma unroll
            for (int e = 0; e < 4; e++) {
                int q = (e < 2) ? qr0 : qr1;
                int k = kc0 + (e & 1);
                int dq = q - k;
                float sh;
                if (dq >= 0)       sh = Dp[(size_t)q * S_ + dq];
                else if (dq == -1) sh = 0.f;
                else               sh = Dp[(size_t)(q + 1) * S_ + (S_ + 1 + dq)];
                float t3x = (e & 1) ? t3v.y : t3v.x;
                sc[nt][e] = (sc[nt][e] + t3x + sh) * 0.125f;
            }
            mx0 = fmaxf(mx0, fmaxf(sc[nt][0], sc[nt][1]));
            mx1 = fmaxf(mx1, fmaxf(sc[nt][2], sc[nt][3]));
        }
        mx0 = fmaxf(mx0, __shfl_xor_sync(0xffffffffu, mx0, 1));
        mx0 = fmaxf(mx0, __shfl_xor_sync(0xffffffffu, mx0, 2));
        mx1 = fmaxf(mx1, __shfl_xor_sync(0xffffffffu, mx1, 1));
        mx1 = fmaxf(mx1, __shfl_xor_sync(0xffffffffu, mx1, 2));
        float mn0 = fmaxf(m0r, mx0), mn1 = fmaxf(m1r, mx1);
        float al0 = exp2f((m0r - mn0) * L2E), al1 = exp2f((m1r - mn1) * L2E);
        m0r = mn0; m1r = mn1;

        float sum0 = 0.f, sum1 = 0.f;
        uint32_t hP[8][2];
        #pragma unroll
        for (int nt = 0; nt < 8; nt++) {
            float p0 = exp2f((sc[nt][0] - mn0) * L2E);
            float p1 = exp2f((sc[nt][1] - mn0) * L2E);
            float p2 = exp2f((sc[nt][2] - mn1) * L2E);
            float p3 = exp2f((sc[nt][3] - mn1) * L2E);
            sum0 += p0 + p1; sum1 += p2 + p3;
            hP[nt][0] = packh2(p0, p1);
            hP[nt][1] = packh2(p2, p3);
        }
        sum0 += __shfl_xor_sync(0xffffffffu, sum0, 1);
        sum0 += __shfl_xor_sync(0xffffffffu, sum0, 2);
        sum1 += __shfl_xor_sync(0xffffffffu, sum1, 1);
        sum1 += __shfl_xor_sync(0xffffffffu, sum1, 2);
        l0r = l0r * al0 + sum0;
        l1r = l1r * al1 + sum1;
        #pragma unroll
        for (int nd = 0; nd < 8; nd++) {
            Oa[nd][0] *= al0; Oa[nd][1] *= al0;
            Oa[nd][2] *= al1; Oa[nd][3] *= al1;
        }

        // O += P @ V
        #pragma unroll
        for (int j = 0; j < 4; j++) {
            uint32_t pa0 = hP[2 * j][0], pa1 = hP[2 * j][1];
            uint32_t pa2 = hP[2 * j + 1][0], pa3 = hP[2 * j + 1][1];
            #pragma unroll
            for (int dp = 0; dp < 4; dp++) {
                uint32_t ad = cvtsm(&Vs[buf * 4608 + (j * 16 + (lane & 15)) * 72
                                        + dp * 16 + 8 * (lane >> 4)]);
                uint32_t r0, r1, r2, r3;
                ldsm4t(r0, r1, r2, r3, ad);
                mma16(Oa[dp * 2], pa0, pa1, pa2, pa3, r0, r1);
                mma16(Oa[dp * 2 + 1], pa0, pa1, pa2, pa3, r2, r3);
            }
        }
        __syncthreads();
    }

    float inv0 = 1.f / l0r, inv1 = 1.f / l1r;
    #pragma unroll
    for (int nd = 0; nd < 8; nd++) {
        int d = nd * 8 + tig * 2;
        *(__half2*)&CTXh[((size_t)b * S_ + qr0) * C_ + h * D_ + d] =
            __floats2half2_rn(Oa[nd][0] * inv0, Oa[nd][1] * inv0);
        *(__half2*)&CTXh[((size_t)b * S_ + qr1) * C_ + h * D_ + d] =
            __floats2half2_rn(Oa[nd][2] * inv1, Oa[nd][3] * inv1);
    }
}

// ---------------- launch ----------------
extern "C" void kernel_launch(void* const* d_in, const int* in_sizes, int n_in,
                              void* d_out, int out_size)
{
    const float* x  = (const float*)d_in[0];
    const float* Wq = (const float*)d_in[1];
    const float* Wk = (const float*)d_in[2];
    const float* Wv = (const float*)d_in[3];
    const float* u  = (const float*)d_in[4];
    const float* v  = (const float*)d_in[5];
    const float* Wo = (const float*)d_in[6];
    const float* bo = (const float*)d_in[7];
    float* out = (float*)d_out;

    __half *xh, *Wqh, *Wkh, *Wvh, *Woh, *rrh, *Qh, *Kh, *Vh, *CTXh;
    float *T3, *D;
    cudaGetSymbolAddress((void**)&xh,   g_xh);
    cudaGetSymbolAddress((void**)&Wqh,  g_Wqh);
    cudaGetSymbolAddress((void**)&Wkh,  g_Wkh);
    cudaGetSymbolAddress((void**)&Wvh,  g_Wvh);
    cudaGetSymbolAddress((void**)&Woh,  g_Woh);
    cudaGetSymbolAddress((void**)&rrh,  g_rrh);
    cudaGetSymbolAddress((void**)&Qh,   g_Qh);
    cudaGetSymbolAddress((void**)&Kh,   g_Kh);
    cudaGetSymbolAddress((void**)&Vh,   g_Vh);
    cudaGetSymbolAddress((void**)&T3,   g_T3);
    cudaGetSymbolAddress((void**)&D,    g_D);
    cudaGetSymbolAddress((void**)&CTXh, g_CTXh);

    static int smem_set = 0;
    const int SMEMP = 2 * 128 * 72 * 2 + 2 * 32 * 136 * 2;            // 54272
    const int SMEMF = 128 * 72 * 2 + 4 * 64 * 72 * 2 + 2 * 64 * 4;    // 55808
    if (!smem_set) {
        cudaFuncSetAttribute(gemm_f16, cudaFuncAttributeMaxDynamicSharedMemorySize, SMEMP);
        cudaFuncSetAttribute(flash_kernel, cudaFuncAttributeMaxDynamicSharedMemorySize, SMEMF);
        smem_set = 1;
    }

    const int NTOT = B_ * S_ * C_ + 4 * C_ * C_;   // 8388608
    cvt_all<<<NTOT / 1024, 256>>>(x, Wq, Wk, Wv, Wo, xh, Wqh, Wkh, Wvh, Woh);
    rr_kernel<<<S_, 64>>>(rrh);

    dim3 gproj(C_ / 128, (B_ * S_) / 128);
    gemm_f16<<<gproj, 256, SMEMP>>>(xh, Wqh, nullptr, Qh, B_ * S_, C_, C_, 1);
    gemm_f16<<<gproj, 256, SMEMP>>>(xh, Wkh, nullptr, Kh, B_ * S_, C_, C_, 1);
    gemm_f16<<<gproj, 256, SMEMP>>>(xh, Wvh, nullptr, Vh, B_ * S_, C_, C_, 1);

    t3_kernel<<<(BH_ * S_ * 32) / 256, 256>>>(Kh, u, T3);

    dim3 gd(S_ / 128, S_ / 128, BH_);
    relD_f16<<<gd, 256>>>(Qh, rrh, v, D);

    dim3 gfl(S_ / 128, BH_);
    flash_kernel<<<gfl, 256, SMEMF>>>(Qh, Kh, Vh, T3, D, CTXh);

    gemm_f16<<<gproj, 256, SMEMP>>>(CTXh, Woh, bo, out, B_ * S_, C_, C_, 0);
}

// round 6
// speedup vs baseline: 2.6093x; 1.5134x over previous
#include <cuda_runtime.h>
#include <cuda_fp16.h>
#include <math.h>
#include <stdint.h>

#define B_ 2
#define S_ 2048
#define C_ 1024
#define H_ 16
#define D_ 64
#define BH_ (B_*H_)
#define L2E 1.4426950408889634f

// ---------------- scratch ----------------
__device__ __half g_xh[(size_t)B_*S_*C_];
__device__ __half g_Wqh[C_*C_];
__device__ __half g_Wkh[C_*C_];
__device__ __half g_Wvh[C_*C_];
__device__ __half g_Woh[C_*C_];
__device__ __half g_rrh[S_*D_];
__device__ __half g_Qh[(size_t)BH_*S_*D_];
__device__ __half g_Kh[(size_t)BH_*S_*D_];
__device__ __half g_Vh[(size_t)BH_*S_*D_];
__device__ float  g_T3[BH_*S_];
__device__ __half g_SHD[(size_t)BH_*S_*S_];   // PRE-SHIFTED rel-pos scores, fp16
__device__ __half g_CTXh[(size_t)B_*S_*C_];

// ---------------- asm helpers ----------------
__device__ __forceinline__ uint32_t cvtsm(const void* p) {
    return (uint32_t)__cvta_generic_to_shared(p);
}
#define CP16(dst, src) asm volatile("cp.async.cg.shared.global [%0],[%1],16;\n" :: "r"(dst), "l"(src))
#define CPCOMMIT()     asm volatile("cp.async.commit_group;\n")
#define CPWAIT(n)      asm volatile("cp.async.wait_group %0;\n" :: "n"(n))

__device__ __forceinline__ void ldsm4(uint32_t& r0, uint32_t& r1, uint32_t& r2, uint32_t& r3, uint32_t a) {
    asm volatile("ldmatrix.sync.aligned.m8n8.x4.shared.b16 {%0,%1,%2,%3},[%4];\n"
                 : "=r"(r0), "=r"(r1), "=r"(r2), "=r"(r3) : "r"(a));
}
__device__ __forceinline__ void ldsm4t(uint32_t& r0, uint32_t& r1, uint32_t& r2, uint32_t& r3, uint32_t a) {
    asm volatile("ldmatrix.sync.aligned.m8n8.x4.trans.shared.b16 {%0,%1,%2,%3},[%4];\n"
                 : "=r"(r0), "=r"(r1), "=r"(r2), "=r"(r3) : "r"(a));
}
__device__ __forceinline__ void mma16(float* c, uint32_t a0, uint32_t a1, uint32_t a2, uint32_t a3,
                                      uint32_t b0, uint32_t b1) {
    asm volatile("mma.sync.aligned.m16n8k16.row.col.f32.f16.f16.f32 "
                 "{%0,%1,%2,%3},{%4,%5,%6,%7},{%8,%9},{%0,%1,%2,%3};\n"
                 : "+f"(c[0]), "+f"(c[1]), "+f"(c[2]), "+f"(c[3])
                 : "r"(a0), "r"(a1), "r"(a2), "r"(a3), "r"(b0), "r"(b1));
}
__device__ __forceinline__ uint32_t packh2(float a, float b) {
    __half2 h = __floats2half2_rn(a, b);
    return *(uint32_t*)&h;
}

// ---------------- fused fp32 -> fp16 convert (x + 4 weights) ----------------
__global__ void cvt_all(const float* __restrict__ x,  const float* __restrict__ Wq,
                        const float* __restrict__ Wk, const float* __restrict__ Wv,
                        const float* __restrict__ Wo,
                        __half* __restrict__ xh,  __half* __restrict__ Wqh,
                        __half* __restrict__ Wkh, __half* __restrict__ Wvh,
                        __half* __restrict__ Woh)
{
    int i = (blockIdx.x * blockDim.x + threadIdx.x) * 4;
    const float* src; __half* dst; int off;
    const int NX = B_ * S_ * C_;
    const int NW = C_ * C_;
    if (i < NX)               { src = x;  dst = xh;  off = i; }
    else if (i < NX + NW)     { src = Wq; dst = Wqh; off = i - NX; }
    else if (i < NX + 2 * NW) { src = Wk; dst = Wkh; off = i - NX - NW; }
    else if (i < NX + 3 * NW) { src = Wv; dst = Wvh; off = i - NX - 2 * NW; }
    else                      { src = Wo; dst = Woh; off = i - NX - 3 * NW; }
    float4 v = *(const float4*)(src + off);
    *(__half2*)(dst + off)     = __floats2half2_rn(v.x, v.y);
    *(__half2*)(dst + off + 2) = __floats2half2_rn(v.z, v.w);
}

// ---------------- sinusoid rel-pos table (fp16) ----------------
__global__ void rr_kernel(__half* __restrict__ rr) {
    int p = blockIdx.x;
    int i = threadIdx.x;
    double invf = exp(-((double)(i & 31)) * (log(10000.0) / 32.0));
    double ang = (double)p * invf;
    float v = (i < 32) ? (float)sin(ang) : (float)cos(ang);
    rr[p * D_ + i] = __float2half(v);
}

// ---------------- fp16 GEMM NN: C = A[M,K] @ B[K,N]; mode1: half headed out; mode0: f32+bias ----------------
__global__ __launch_bounds__(256) void gemm_f16(
    const __half* __restrict__ A, const __half* __restrict__ Bm,
    const float* __restrict__ bias, void* __restrict__ Co,
    int M, int N, int K, int mode)
{
    extern __shared__ __half sm[];
    __half* As = sm;                 // [2][128][72]
    __half* Bs = sm + 2 * 128 * 72;  // [2][32][136]
    const int tid = threadIdx.x, lane = tid & 31, warp = tid >> 5;
    const int wm = warp >> 2, wn = warp & 3, grp = lane >> 2, tig = lane & 3;
    const int m0 = blockIdx.y * 128, n0 = blockIdx.x * 128;

    float acc[4][4][4];
    #pragma unroll
    for (int i = 0; i < 4; i++)
        #pragma unroll
        for (int j = 0; j < 4; j++)
            #pragma unroll
            for (int e = 0; e < 4; e++) acc[i][j][e] = 0.f;

    #define CPA(buf, kt) { \
        _Pragma("unroll") \
        for (int i_ = 0; i_ < 2; i_++) { int cid = tid + i_ * 256; int r = cid >> 2, c = cid & 3; \
            CP16(cvtsm(&As[(buf) * 128 * 72 + r * 72 + c * 8]), A + (size_t)(m0 + r) * K + (kt) + c * 8); } }
    #define CPB(buf, kt) { \
        _Pragma("unroll") \
        for (int i_ = 0; i_ < 2; i_++) { int cid = tid + i_ * 256; int r = cid >> 4, c = cid & 15; \
            CP16(cvtsm(&Bs[(buf) * 32 * 136 + r * 136 + c * 8]), Bm + (size_t)((kt) + r) * N + n0 + c * 8); } }

    CPA(0, 0); CPB(0, 0); CPCOMMIT();

    const int nk = K / 32;
    for (int it = 0; it < nk; it++) {
        int buf = it & 1;
        if (it + 1 < nk) { CPA(buf ^ 1, (it + 1) * 32); CPB(buf ^ 1, (it + 1) * 32); CPCOMMIT(); CPWAIT(1); }
        else CPWAIT(0);
        __syncthreads();

        #pragma unroll
        for (int kc = 0; kc < 32; kc += 16) {
            uint32_t a[4][4];
            #pragma unroll
            for (int mi = 0; mi < 4; mi++) {
                uint32_t ad = cvtsm(&As[buf * 128 * 72 + (wm * 64 + mi * 16 + (lane & 15)) * 72 + kc + 8 * (lane >> 4)]);
                ldsm4(a[mi][0], a[mi][1], a[mi][2], a[mi][3], ad);
            }
            uint32_t b[4][2];
            #pragma unroll
            for (int np = 0; np < 2; np++) {
                uint32_t ad = cvtsm(&Bs[buf * 32 * 136 + (kc + (lane & 7) + 8 * ((lane >> 3) & 1)) * 136
                                        + wn * 32 + np * 16 + 8 * (lane >> 4)]);
                uint32_t r0, r1, r2, r3;
                ldsm4t(r0, r1, r2, r3, ad);
                b[np * 2][0] = r0; b[np * 2][1] = r1;
                b[np * 2 + 1][0] = r2; b[np * 2 + 1][1] = r3;
            }
            #pragma unroll
            for (int mi = 0; mi < 4; mi++)
                #pragma unroll
                for (int ni = 0; ni < 4; ni++)
                    mma16(acc[mi][ni], a[mi][0], a[mi][1], a[mi][2], a[mi][3], b[ni][0], b[ni][1]);
        }
        __syncthreads();
    }

    #pragma unroll
    for (int mi = 0; mi < 4; mi++)
        #pragma unroll
        for (int ni = 0; ni < 4; ni++) {
            int m = m0 + wm * 64 + mi * 16 + grp;
            int n = n0 + wn * 32 + ni * 8 + tig * 2;
            if (mode == 1) {
                __half* O = (__half*)Co;
                int b = m >> 11, h = n >> 6, d = n & 63;
                int s0 = m & (S_ - 1);
                *(__half2*)&O[(((size_t)(b * H_ + h)) * S_ + s0) * D_ + d] =
                    __floats2half2_rn(acc[mi][ni][0], acc[mi][ni][1]);
                *(__half2*)&O[(((size_t)(b * H_ + h)) * S_ + s0 + 8) * D_ + d] =
                    __floats2half2_rn(acc[mi][ni][2], acc[mi][ni][3]);
            } else {
                float* O = (float*)Co;
                float b0v = bias[n], b1v = bias[n + 1];
                *(float2*)&O[(size_t)m * N + n] = make_float2(acc[mi][ni][0] + b0v, acc[mi][ni][1] + b1v);
                *(float2*)&O[(size_t)(m + 8) * N + n] = make_float2(acc[mi][ni][2] + b0v, acc[mi][ni][3] + b1v);
            }
        }
}

// ---------------- T3[bh][k] = u[h] . K[bh][k] ----------------
__global__ void t3_kernel(const __half* __restrict__ Km, const float* __restrict__ u,
                          float* __restrict__ T3)
{
    int warp = (blockIdx.x * blockDim.x + threadIdx.x) >> 5;
    int lane = threadIdx.x & 31;
    if (warp >= BH_ * S_) return;
    int bh = warp >> 11;
    int h = bh & (H_ - 1);
    const __half* kr = Km + (size_t)warp * D_;
    float s = __half2float(kr[lane]) * u[h * D_ + lane]
            + __half2float(kr[lane + 32]) * u[h * D_ + lane + 32];
    #pragma unroll
    for (int o = 16; o; o >>= 1) s += __shfl_xor_sync(0xffffffffu, s, o);
    if (lane == 0) T3[warp] = s;
}

// ---------------- relD: D = (Q+v) @ rr^T, written PRE-SHIFTED to SHD (fp16) ----------------
// D[q][p]:  p<=q  -> SHD[q][q-p]
//           p> q  -> SHD[q-1][S+q-p]       (q>0; q==0 discarded)
// diag thread (p==q) also writes SHD[q][q+1] = 0.
__global__ __launch_bounds__(256) void relD_f16(
    const __half* __restrict__ Qh, const __half* __restrict__ rrh,
    const float* __restrict__ vb, __half* __restrict__ SHDg)
{
    __shared__ __half As[128 * 72];
    __shared__ __half Bs[128 * 72];
    const int bh = blockIdx.z, h = bh & (H_ - 1);
    const int q0 = blockIdx.y * 128, p0 = blockIdx.x * 128;
    const __half* Aq = Qh + (size_t)bh * S_ * D_;
    const int tid = threadIdx.x, lane = tid & 31, warp = tid >> 5;
    const int wm = warp >> 2, wn = warp & 3, grp = lane >> 2, tig = lane & 3;

    {
        int r = tid >> 1, off = (tid & 1) * 32;
        const __half* src = Aq + (size_t)(q0 + r) * D_ + off;
        #pragma unroll
        for (int i = 0; i < 32; i += 2) {
            float2 qv = __half22float2(*(const __half2*)(src + i));
            float2 vv = *(const float2*)(vb + h * D_ + off + i);
            *(__half2*)&As[r * 72 + off + i] = __floats2half2_rn(qv.x + vv.x, qv.y + vv.y);
        }
    }
    #pragma unroll
    for (int i = 0; i < 4; i++) {
        int cid = tid + i * 256;
        int r = cid >> 3, c = cid & 7;
        *(uint4*)&Bs[r * 72 + c * 8] = *(const uint4*)(rrh + (size_t)(p0 + r) * D_ + c * 8);
    }
    __syncthreads();

    float acc[4][4][4];
    #pragma unroll
    for (int i = 0; i < 4; i++)
        #pragma unroll
        for (int j = 0; j < 4; j++)
            #pragma unroll
            for (int e = 0; e < 4; e++) acc[i][j][e] = 0.f;

    #pragma unroll
    for (int kc = 0; kc < 64; kc += 16) {
        uint32_t a[4][4];
        #pragma unroll
        for (int mi = 0; mi < 4; mi++) {
            uint32_t ad = cvtsm(&As[(wm * 64 + mi * 16 + (lane & 15)) * 72 + kc + 8 * (lane >> 4)]);
            ldsm4(a[mi][0], a[mi][1], a[mi][2], a[mi][3], ad);
        }
        uint32_t b[4][2];
        #pragma unroll
        for (int np = 0; np < 2; np++) {
            uint32_t ad = cvtsm(&Bs[(wn * 32 + np * 16 + (lane & 7) + 8 * (lane >> 4)) * 72
                                    + kc + 8 * ((lane >> 3) & 1)]);
            uint32_t r0, r1, r2, r3;
            ldsm4(r0, r1, r2, r3, ad);
            b[np * 2][0] = r0; b[np * 2][1] = r1;
            b[np * 2 + 1][0] = r2; b[np * 2 + 1][1] = r3;
        }
        #pragma unroll
        for (int mi = 0; mi < 4; mi++)
            #pragma unroll
            for (int ni = 0; ni < 4; ni++)
                mma16(acc[mi][ni], a[mi][0], a[mi][1], a[mi][2], a[mi][3], b[ni][0], b[ni][1]);
    }

    __half* SHD = SHDg + (size_t)bh * S_ * S_;
    #pragma unroll
    for (int mi = 0; mi < 4; mi++)
        #pragma unroll
        for (int ni = 0; ni < 4; ni++) {
            #pragma unroll
            for (int e = 0; e < 4; e++) {
                int q = q0 + wm * 64 + mi * 16 + grp + (e >> 1) * 8;
                int p = p0 + wn * 32 + ni * 8 + tig * 2 + (e & 1);
                __half hv = __float2half(acc[mi][ni][e]);
                if (p <= q) {
                    SHD[(size_t)q * S_ + (q - p)] = hv;
                    if (p == q && q + 1 < S_)
                        SHD[(size_t)q * S_ + q + 1] = __float2half(0.f);
                } else if (q > 0) {
                    SHD[(size_t)(q - 1) * S_ + (S_ + q - p)] = hv;
                }
            }
        }
}

// ---------------- fused flash attention: BM=128, BN=64, SHD streamed via cp.async ----------------
__global__ __launch_bounds__(256, 2) void flash_kernel(
    const __half* __restrict__ Qh, const __half* __restrict__ Kh, const __half* __restrict__ Vh,
    const float* __restrict__ T3, const __half* __restrict__ SHDg, __half* __restrict__ CTXh)
{
    extern __shared__ __half sm[];
    __half* Qs = sm;                             // [128][72]
    __half* Ks = sm + 9216;                      // [2][64][72]
    __half* Vs = Ks + 9216;                      // [2][64][72]
    __half* Ss = Vs + 9216;                      // [2][128][72] shifted-D tiles
    float*  T3s = (float*)(Ss + 18432);          // [2][64]

    const int bh = blockIdx.y, b = bh >> 4, h = bh & 15;
    const int q0 = blockIdx.x * 128;
    const __half* Qg = Qh + (size_t)bh * S_ * D_;
    const __half* Kg = Kh + (size_t)bh * S_ * D_;
    const __half* Vg = Vh + (size_t)bh * S_ * D_;
    const __half* SHp = SHDg + (size_t)bh * S_ * S_;
    const float* t3g = T3 + bh * S_;
    const int tid = threadIdx.x, lane = tid & 31, warp = tid >> 5;
    const int grp = lane >> 2, tig = lane & 3;
    const int wrow = warp * 16;

    #pragma unroll
    for (int i = 0; i < 4; i++) {
        int cid = tid + i * 256, r = cid >> 3, c = cid & 7;
        CP16(cvtsm(&Qs[r * 72 + c * 8]), Qg + (size_t)(q0 + r) * D_ + c * 8);
    }
    #define CPKV(buf, k0t) { \
        _Pragma("unroll") \
        for (int i_ = 0; i_ < 2; i_++) { int cid = tid + i_ * 256, r = cid >> 3, c = cid & 7; \
            CP16(cvtsm(&Ks[(buf) * 4608 + r * 72 + c * 8]), Kg + (size_t)((k0t) + r) * D_ + c * 8); } \
        _Pragma("unroll") \
        for (int i_ = 0; i_ < 2; i_++) { int cid = tid + i_ * 256, r = cid >> 3, c = cid & 7; \
            CP16(cvtsm(&Vs[(buf) * 4608 + r * 72 + c * 8]), Vg + (size_t)((k0t) + r) * D_ + c * 8); } \
        _Pragma("unroll") \
        for (int i_ = 0; i_ < 4; i_++) { int cid = tid + i_ * 256, r = cid >> 3, c = cid & 7; \
            CP16(cvtsm(&Ss[(buf) * 9216 + r * 72 + c * 8]), SHp + (size_t)(q0 + r) * S_ + (k0t) + c * 8); } \
        if (tid < 16) CP16(cvtsm(&T3s[(buf) * 64 + tid * 4]), t3g + (k0t) + tid * 4); }

    CPKV(0, 0); CPCOMMIT();
    CPWAIT(0);
    __syncthreads();

    uint32_t aQ[4][4];
    #pragma unroll
    for (int kc = 0; kc < 4; kc++) {
        uint32_t ad = cvtsm(&Qs[(wrow + (lane & 15)) * 72 + kc * 16 + 8 * (lane >> 4)]);
        ldsm4(aQ[kc][0], aQ[kc][1], aQ[kc][2], aQ[kc][3], ad);
    }

    float Oa[8][4];
    #pragma unroll
    for (int i = 0; i < 8; i++)
        #pragma unroll
        for (int e = 0; e < 4; e++) Oa[i][e] = 0.f;
    float m0r = -1e30f, m1r = -1e30f, l0r = 0.f, l1r = 0.f;
    const int qr0 = q0 + wrow + grp, qr1 = qr0 + 8;
    const int sr0 = (wrow + grp) * 72, sr1 = sr0 + 8 * 72;

    for (int kt = 0; kt < 32; kt++) {
        const int buf = kt & 1;
        if (kt < 31) { CPKV(buf ^ 1, (kt + 1) * 64); CPCOMMIT(); CPWAIT(1); }
        else CPWAIT(0);
        __syncthreads();

        // S = Q @ K^T  (16 rows x 64 cols per warp)
        float sc[8][4];
        #pragma unroll
        for (int i = 0; i < 8; i++)
            #pragma unroll
            for (int e = 0; e < 4; e++) sc[i][e] = 0.f;
        #pragma unroll
        for (int ntp = 0; ntp < 4; ntp++) {
            #pragma unroll
            for (int kc = 0; kc < 4; kc++) {
                uint32_t ad = cvtsm(&Ks[buf * 4608 + (ntp * 16 + (lane & 7) + 8 * (lane >> 4)) * 72
                                        + kc * 16 + 8 * ((lane >> 3) & 1)]);
                uint32_t r0, r1, r2, r3;
                ldsm4(r0, r1, r2, r3, ad);
                mma16(sc[ntp * 2], aQ[kc][0], aQ[kc][1], aQ[kc][2], aQ[kc][3], r0, r1);
                mma16(sc[ntp * 2 + 1], aQ[kc][0], aQ[kc][1], aQ[kc][2], aQ[kc][3], r2, r3);
            }
        }

        // epilogue: + t3 + shifted-D (from smem), scale, online softmax
        float mx0 = -1e30f, mx1 = -1e30f;
        #pragma unroll
        for (int nt = 0; nt < 8; nt++) {
            int col = nt * 8 + tig * 2;
            float2 t3v = *(float2*)&T3s[buf * 64 + col];
            float2 s0 = __half22float2(*(__half2*)&Ss[buf * 9216 + sr0 + col]);
            float2 s1 = __half22float2(*(__half2*)&Ss[buf * 9216 + sr1 + col]);
            sc[nt][0] = (sc[nt][0] + t3v.x + s0.x) * 0.125f;
            sc[nt][1] = (sc[nt][1] + t3v.y + s0.y) * 0.125f;
            sc[nt][2] = (sc[nt][2] + t3v.x + s1.x) * 0.125f;
            sc[nt][3] = (sc[nt][3] + t3v.y + s1.y) * 0.125f;
            mx0 = fmaxf(mx0, fmaxf(sc[nt][0], sc[nt][1]));
            mx1 = fmaxf(mx1, fmaxf(sc[nt][2], sc[nt][3]));
        }
        mx0 = fmaxf(mx0, __shfl_xor_sync(0xffffffffu, mx0, 1));
        mx0 = fmaxf(mx0, __shfl_xor_sync(0xffffffffu, mx0, 2));
        mx1 = fmaxf(mx1, __shfl_xor_sync(0xffffffffu, mx1, 1));
        mx1 = fmaxf(mx1, __shfl_xor_sync(0xffffffffu, mx1, 2));
        float mn0 = fmaxf(m0r, mx0), mn1 = fmaxf(m1r, mx1);
        float al0 = exp2f((m0r - mn0) * L2E), al1 = exp2f((m1r - mn1) * L2E);
        m0r = mn0; m1r = mn1;

        float sum0 = 0.f, sum1 = 0.f;
        uint32_t hP[8][2];
        #pragma unroll
        for (int nt = 0; nt < 8; nt++) {
            float p0 = exp2f((sc[nt][0] - mn0) * L2E);
            float p1 = exp2f((sc[nt][1] - mn0) * L2E);
            float p2 = exp2f((sc[nt][2] - mn1) * L2E);
            float p3 = exp2f((sc[nt][3] - mn1) * L2E);
            sum0 += p0 + p1; sum1 += p2 + p3;
            hP[nt][0] = packh2(p0, p1);
            hP[nt][1] = packh2(p2, p3);
        }
        sum0 += __shfl_xor_sync(0xffffffffu, sum0, 1);
        sum0 += __shfl_xor_sync(0xffffffffu, sum0, 2);
        sum1 += __shfl_xor_sync(0xffffffffu, sum1, 1);
        sum1 += __shfl_xor_sync(0xffffffffu, sum1, 2);
        l0r = l0r * al0 + sum0;
        l1r = l1r * al1 + sum1;
        #pragma unroll
        for (int nd = 0; nd < 8; nd++) {
            Oa[nd][0] *= al0; Oa[nd][1] *= al0;
            Oa[nd][2] *= al1; Oa[nd][3] *= al1;
        }

        // O += P @ V
        #pragma unroll
        for (int j = 0; j < 4; j++) {
            uint32_t pa0 = hP[2 * j][0], pa1 = hP[2 * j][1];
            uint32_t pa2 = hP[2 * j + 1][0], pa3 = hP[2 * j + 1][1];
            #pragma unroll
            for (int dp = 0; dp < 4; dp++) {
                uint32_t ad = cvtsm(&Vs[buf * 4608 + (j * 16 + (lane & 15)) * 72
                                        + dp * 16 + 8 * (lane >> 4)]);
                uint32_t r0, r1, r2, r3;
                ldsm4t(r0, r1, r2, r3, ad);
                mma16(Oa[dp * 2], pa0, pa1, pa2, pa3, r0, r1);
                mma16(Oa[dp * 2 + 1], pa0, pa1, pa2, pa3, r2, r3);
            }
        }
        __syncthreads();
    }

    float inv0 = 1.f / l0r, inv1 = 1.f / l1r;
    #pragma unroll
    for (int nd = 0; nd < 8; nd++) {
        int d = nd * 8 + tig * 2;
        *(__half2*)&CTXh[((size_t)b * S_ + qr0) * C_ + h * D_ + d] =
            __floats2half2_rn(Oa[nd][0] * inv0, Oa[nd][1] * inv0);
        *(__half2*)&CTXh[((size_t)b * S_ + qr1) * C_ + h * D_ + d] =
            __floats2half2_rn(Oa[nd][2] * inv1, Oa[nd][3] * inv1);
    }
}

// ---------------- launch ----------------
extern "C" void kernel_launch(void* const* d_in, const int* in_sizes, int n_in,
                              void* d_out, int out_size)
{
    const float* x  = (const float*)d_in[0];
    const float* Wq = (const float*)d_in[1];
    const float* Wk = (const float*)d_in[2];
    const float* Wv = (const float*)d_in[3];
    const float* u  = (const float*)d_in[4];
    const float* v  = (const float*)d_in[5];
    const float* Wo = (const float*)d_in[6];
    const float* bo = (const float*)d_in[7];
    float* out = (float*)d_out;

    __half *xh, *Wqh, *Wkh, *Wvh, *Woh, *rrh, *Qh, *Kh, *Vh, *SHD, *CTXh;
    float *T3;
    cudaGetSymbolAddress((void**)&xh,   g_xh);
    cudaGetSymbolAddress((void**)&Wqh,  g_Wqh);
    cudaGetSymbolAddress((void**)&Wkh,  g_Wkh);
    cudaGetSymbolAddress((void**)&Wvh,  g_Wvh);
    cudaGetSymbolAddress((void**)&Woh,  g_Woh);
    cudaGetSymbolAddress((void**)&rrh,  g_rrh);
    cudaGetSymbolAddress((void**)&Qh,   g_Qh);
    cudaGetSymbolAddress((void**)&Kh,   g_Kh);
    cudaGetSymbolAddress((void**)&Vh,   g_Vh);
    cudaGetSymbolAddress((void**)&T3,   g_T3);
    cudaGetSymbolAddress((void**)&SHD,  g_SHD);
    cudaGetSymbolAddress((void**)&CTXh, g_CTXh);

    static int smem_set = 0;
    const int SMEMP = 2 * 128 * 72 * 2 + 2 * 32 * 136 * 2;                      // 54272
    const int SMEMF = (9216 + 9216 + 9216 + 18432) * 2 + 2 * 64 * 4;            // 92672
    if (!smem_set) {
        cudaFuncSetAttribute(gemm_f16, cudaFuncAttributeMaxDynamicSharedMemorySize, SMEMP);
        cudaFuncSetAttribute(flash_kernel, cudaFuncAttributeMaxDynamicSharedMemorySize, SMEMF);
        smem_set = 1;
    }

    const int NTOT = B_ * S_ * C_ + 4 * C_ * C_;
    cvt_all<<<NTOT / 1024, 256>>>(x, Wq, Wk, Wv, Wo, xh, Wqh, Wkh, Wvh, Woh);
    rr_kernel<<<S_, 64>>>(rrh);

    dim3 gproj(C_ / 128, (B_ * S_) / 128);
    gemm_f16<<<gproj, 256, SMEMP>>>(xh, Wqh, nullptr, Qh, B_ * S_, C_, C_, 1);
    gemm_f16<<<gproj, 256, SMEMP>>>(xh, Wkh, nullptr, Kh, B_ * S_, C_, C_, 1);
    gemm_f16<<<gproj, 256, SMEMP>>>(xh, Wvh, nullptr, Vh, B_ * S_, C_, C_, 1);

    t3_kernel<<<(BH_ * S_ * 32) / 256, 256>>>(Kh, u, T3);

    dim3 gd(S_ / 128, S_ / 128, BH_);
    relD_f16<<<gd, 256>>>(Qh, rrh, v, SHD);

    dim3 gfl(S_ / 128, BH_);
    flash_kernel<<<gfl, 256, SMEMF>>>(Qh, Kh, Vh, T3, SHD, CTXh);

    gemm_f16<<<gproj, 256, SMEMP>>>(CTXh, Woh, bo, out, B_ * S_, C_, C_, 0);
}